// round 1
// baseline (speedup 1.0000x reference)
#include <cuda_runtime.h>
#include <math.h>

// ---------------- problem constants ----------------
#define Bn   4
#define Hn   96
#define Wn   320
#define HWn  30720            // 96*320
#define CINn 64
#define HCn  256
#define NCn  3
#define Kn   100

// output layout: concat of raveled (heat, dep, dim, rot, scores, up_pois, reg3d)
#define MAP_N      (Bn*HCn*HWn)          // 31,457,280
#define HEAT_N     (Bn*NCn*HWn)          // 368,640
#define OFF_HEAT   0
#define OFF_DEP    (OFF_HEAT + HEAT_N)
#define OFF_DIM    (OFF_DEP + MAP_N)
#define OFF_ROT    (OFF_DIM + MAP_N)
#define OFF_SCORES (OFF_ROT + MAP_N)     // 94,740,480
#define OFF_POIS   (OFF_SCORES + Bn*Kn)  // 94,740,880
#define OFF_REG3D  (OFF_POIS + Bn*Kn*384)// 94,894,480
#define REG3D_N    (8*8*64*320)          // 1,310,720

// ---------------- device scratch ----------------
__device__ float g_hmh[Bn*HCn*HWn];      // hm head conv output (intermediate)
__device__ float g_nms[HEAT_N];          // NMS'd heat (destroyed by topk)
__device__ float g_alpha[4*HCn];
__device__ float g_beta[4*HCn];
__device__ float g_cval[Bn*NCn*Kn];      // per-(b,c) top-100 values
__device__ int   g_cind[Bn*NCn*Kn];      // per-(b,c) top-100 hw indices
__device__ int   g_sel[Bn*Kn];           // final selected hw indices
__device__ float g_rs[8];                // reg3d row sums

// ---------------- prep: fold BN into alpha/beta, reg3d rowsums ----------------
__global__ void prep_kernel(
    const float* b1_0, const float* g_0, const float* be_0, const float* m_0, const float* v_0,
    const float* b1_1, const float* g_1, const float* be_1, const float* m_1, const float* v_1,
    const float* b1_2, const float* g_2, const float* be_2, const float* m_2, const float* v_2,
    const float* b1_3, const float* g_3, const float* be_3, const float* m_3, const float* v_3,
    const float* r3w)
{
    int t = threadIdx.x;
    const float* B1[4] = {b1_0, b1_1, b1_2, b1_3};
    const float* G [4] = {g_0,  g_1,  g_2,  g_3 };
    const float* BE[4] = {be_0, be_1, be_2, be_3};
    const float* M [4] = {m_0,  m_1,  m_2,  m_3 };
    const float* V [4] = {v_0,  v_1,  v_2,  v_3 };
    int h = t >> 8, c = t & 255;
    float inv = G[h][c] * rsqrtf(V[h][c] + 1e-5f);
    g_alpha[t] = inv;
    g_beta[t]  = (B1[h][c] - M[h][c]) * inv + BE[h][c];
    if (t < 8) {
        float s = 0.f;
        for (int i = 0; i < 64; ++i) s += r3w[t*64 + i];
        g_rs[t] = s;
    }
}

// ---------------- conv3x3 + BN + ReLU (direct, fp32) ----------------
// block: 256 threads = 64 x-positions * 4 oc-groups; each thread: 8 oc * 4 rows
// grid: (W/64=5, H/4=24, B*8=32)
__global__ __launch_bounds__(256) void conv3x3_bn_relu(
    const float* __restrict__ X, const float* __restrict__ Wt,
    int head, float* __restrict__ Yarg)
{
    float* Y = (Yarg != nullptr) ? Yarg : g_hmh;
    const float* alpha = g_alpha + head*HCn;
    const float* beta  = g_beta  + head*HCn;

    const int tx  = threadIdx.x & 63;
    const int ty  = threadIdx.x >> 6;      // 0..3
    const int x0  = blockIdx.x * 64;
    const int y0  = blockIdx.y * 4;
    const int ocb = blockIdx.z & 7;
    const int b   = blockIdx.z >> 3;
    const int oc0 = ocb * 32;

    __shared__ float sIn[8][6][68];
    __shared__ float sW[32][8][9];

    float acc[8][4];
    #pragma unroll
    for (int o = 0; o < 8; ++o)
        #pragma unroll
        for (int yy = 0; yy < 4; ++yy) acc[o][yy] = 0.f;

    const float* Xb = X + (long long)b * CINn * HWn;

    for (int c0 = 0; c0 < CINn; c0 += 8) {
        __syncthreads();
        // load input tile: 8 ch * 6 rows * 66 cols (zero-padded borders)
        for (int i = threadIdx.x; i < 8*6*66; i += 256) {
            int c   = i / (6*66);
            int r   = (i / 66) % 6;
            int col = i % 66;
            int gy = y0 - 1 + r;
            int gx = x0 - 1 + col;
            float v = 0.f;
            if ((unsigned)gy < (unsigned)Hn && (unsigned)gx < (unsigned)Wn)
                v = Xb[(c0 + c) * HWn + gy * Wn + gx];
            sIn[c][r][col] = v;
        }
        // load weights: 32 oc * 8 ch * 9
        for (int i = threadIdx.x; i < 32*8*9; i += 256) {
            int o = i / 72;
            int rem = i % 72;
            int c = rem / 9;
            int k = rem % 9;
            sW[o][c][k] = Wt[(oc0 + o) * (CINn*9) + (c0 + c) * 9 + k];
        }
        __syncthreads();

        for (int c = 0; c < 8; ++c) {
            #pragma unroll
            for (int ky = 0; ky < 3; ++ky) {
                #pragma unroll
                for (int kx = 0; kx < 3; ++kx) {
                    float i0 = sIn[c][ky+0][tx+kx];
                    float i1 = sIn[c][ky+1][tx+kx];
                    float i2 = sIn[c][ky+2][tx+kx];
                    float i3 = sIn[c][ky+3][tx+kx];
                    #pragma unroll
                    for (int o = 0; o < 8; ++o) {
                        float w = sW[ty*8+o][c][ky*3+kx];
                        acc[o][0] = fmaf(i0, w, acc[o][0]);
                        acc[o][1] = fmaf(i1, w, acc[o][1]);
                        acc[o][2] = fmaf(i2, w, acc[o][2]);
                        acc[o][3] = fmaf(i3, w, acc[o][3]);
                    }
                }
            }
        }
    }

    #pragma unroll
    for (int o = 0; o < 8; ++o) {
        int oc = oc0 + ty*8 + o;
        float a  = alpha[oc];
        float bb = beta[oc];
        #pragma unroll
        for (int yy = 0; yy < 4; ++yy) {
            float v = fmaf(acc[o][yy], a, bb);
            v = fmaxf(v, 0.f);
            Y[((b*HCn + oc)*Hn + y0 + yy)*Wn + x0 + tx] = v;
        }
    }
}

// ---------------- hm 1x1 conv (256->3) + sigmoid -> heat ----------------
__global__ __launch_bounds__(256) void heat_kernel(
    const float* __restrict__ w2, const float* __restrict__ b2, float* __restrict__ out)
{
    __shared__ float sw[NCn*HCn];
    int tid = threadIdx.x;
    for (int i = tid; i < NCn*HCn; i += 256) sw[i] = w2[i];
    __syncthreads();
    int b = blockIdx.y;
    int p = blockIdx.x * 256 + tid;
    const float* hp = g_hmh + (long long)b * HCn * HWn + p;
    float s0 = b2[0], s1 = b2[1], s2 = b2[2];
    for (int c = 0; c < HCn; ++c) {
        float h = hp[(long long)c * HWn];
        s0 = fmaf(sw[c],          h, s0);
        s1 = fmaf(sw[HCn + c],    h, s1);
        s2 = fmaf(sw[2*HCn + c],  h, s2);
    }
    out[OFF_HEAT + (b*NCn + 0)*HWn + p] = 1.f / (1.f + expf(-s0));
    out[OFF_HEAT + (b*NCn + 1)*HWn + p] = 1.f / (1.f + expf(-s1));
    out[OFF_HEAT + (b*NCn + 2)*HWn + p] = 1.f / (1.f + expf(-s2));
}

// ---------------- 3x3 maxpool NMS ----------------
__global__ void nms_kernel(const float* __restrict__ heat)
{
    int idx = blockIdx.x * blockDim.x + threadIdx.x;
    if (idx >= HEAT_N) return;
    int bc = idx / HWn;
    int p  = idx - bc * HWn;
    int y = p / Wn, x = p - y * Wn;
    const float* base = heat + bc * HWn;
    float c = base[p];
    float m = c;
    #pragma unroll
    for (int dy = -1; dy <= 1; ++dy) {
        int yy = y + dy;
        if ((unsigned)yy >= (unsigned)Hn) continue;
        #pragma unroll
        for (int dx = -1; dx <= 1; ++dx) {
            int xx = x + dx;
            if ((unsigned)xx >= (unsigned)Wn) continue;
            float v = base[yy * Wn + xx];
            if (v > m) m = v;
        }
    }
    g_nms[idx] = (c == m) ? c : 0.f;
}

// ---------------- per-(b,c) top-100 via 100 block-argmax passes ----------------
__global__ __launch_bounds__(1024) void topk_class_kernel()
{
    int bc  = blockIdx.x;           // 0..11
    int tid = threadIdx.x;
    float v[30];
    const float* src = g_nms + bc * HWn;
    #pragma unroll
    for (int j = 0; j < 30; ++j) v[j] = src[j*1024 + tid];

    __shared__ unsigned long long swarp[32];
    __shared__ unsigned long long swin;

    for (int it = 0; it < Kn; ++it) {
        float bv = -1.f; int bj = 0;
        #pragma unroll
        for (int j = 0; j < 30; ++j) { if (v[j] > bv) { bv = v[j]; bj = j; } }
        unsigned vb = (bv > 0.f) ? __float_as_uint(bv) : 0u;
        unsigned long long key =
            ((unsigned long long)vb << 32) | (unsigned)(bj*1024 + tid);

        unsigned long long k = key;
        #pragma unroll
        for (int off = 16; off > 0; off >>= 1) {
            unsigned long long o = __shfl_down_sync(0xffffffffu, k, off);
            if (o > k) k = o;
        }
        if ((tid & 31) == 0) swarp[tid >> 5] = k;
        __syncthreads();
        if (tid < 32) {
            unsigned long long k2 = swarp[tid];
            #pragma unroll
            for (int off = 16; off > 0; off >>= 1) {
                unsigned long long o = __shfl_down_sync(0xffffffffu, k2, off);
                if (o > k2) k2 = o;
            }
            if (tid == 0) swin = k2;
        }
        __syncthreads();
        unsigned long long win = swin;
        if (tid == 0) {
            g_cval[bc*Kn + it] = __uint_as_float((unsigned)(win >> 32));
            g_cind[bc*Kn + it] = (int)(win & 0xffffffffu);
        }
        if (key == win) {
            #pragma unroll
            for (int j = 0; j < 30; ++j) { if (j == bj) v[j] = -1.f; }
        }
        __syncthreads();
    }
}

// ---------------- per-b merge of 300 candidates -> sorted top-100 ----------------
__global__ __launch_bounds__(256) void merge_kernel(float* __restrict__ out)
{
    int b = blockIdx.x, tid = threadIdx.x;
    __shared__ float sv[300];
    __shared__ int   si[300];
    __shared__ unsigned long long swarp[8];
    for (int i = tid; i < 300; i += 256) {
        int cls = i / Kn, j = i % Kn;
        sv[i] = g_cval[(b*NCn + cls)*Kn + j];
        si[i] = g_cind[(b*NCn + cls)*Kn + j];
    }
    __syncthreads();
    for (int it = 0; it < Kn; ++it) {
        float bv = -1.f; int bi = -1;
        for (int i = tid; i < 300; i += 256) { if (sv[i] > bv) { bv = sv[i]; bi = i; } }
        unsigned vb = (bv > 0.f) ? __float_as_uint(bv) : 0u;
        unsigned long long k = ((unsigned long long)vb << 32) | (unsigned)(bi + 1);
        #pragma unroll
        for (int off = 16; off > 0; off >>= 1) {
            unsigned long long o = __shfl_down_sync(0xffffffffu, k, off);
            if (o > k) k = o;
        }
        if ((tid & 31) == 0) swarp[tid >> 5] = k;
        __syncthreads();
        if (tid == 0) {
            unsigned long long win = swarp[0];
            #pragma unroll
            for (int w = 1; w < 8; ++w) { if (swarp[w] > win) win = swarp[w]; }
            int slot = (int)(win & 0xffffffffu) - 1;
            out[OFF_SCORES + b*Kn + it] = __uint_as_float((unsigned)(win >> 32));
            g_sel[b*Kn + it] = si[slot];
            sv[slot] = -1.f;
        }
        __syncthreads();
    }
}

// ---------------- multi-scale gather -> up_pois ----------------
__global__ __launch_bounds__(384) void gather_kernel(
    const float* __restrict__ up8, const float* __restrict__ up16, float* __restrict__ out)
{
    int bk = blockIdx.x;            // 0..399
    int b  = bk / Kn;
    int c  = threadIdx.x;           // 0..383
    int ind = g_sel[bk];            // in [0, HW)
    if (ind < 0) ind = 0;
    if (ind > HWn - 1) ind = HWn - 1;
    float val;
    if (c < 128)
        val = up8 [((long long)b*128 + c)       * HWn + (ind >> 1)];
    else
        val = up16[((long long)b*256 + (c-128)) * HWn + (ind >> 2)];
    out[OFF_POIS + bk*384 + c] = val;
}

// ---------------- reg3d constant fill ----------------
__global__ void reg3d_kernel(const float* __restrict__ r3b, float* __restrict__ out)
{
    int idx = blockIdx.x * blockDim.x + threadIdx.x;
    if (idx >= REG3D_N) return;
    int o = (idx / (64*320)) & 7;
    out[OFF_REG3D + idx] = g_rs[o] + r3b[o];
}

// ---------------- launch ----------------
extern "C" void kernel_launch(void* const* d_in, const int* in_sizes, int n_in,
                              void* d_out, int out_size)
{
    const float* up16 = (const float*)d_in[0];
    const float* up8  = (const float*)d_in[1];
    const float* up4  = (const float*)d_in[2];

    // per-head params: hm=3..8, dep=9..14, dim=15..20, rot=21..26 (w1,b1,g,be,m,v)
    const float* hm_w1  = (const float*)d_in[3];
    const float* dep_w1 = (const float*)d_in[9];
    const float* dim_w1 = (const float*)d_in[15];
    const float* rot_w1 = (const float*)d_in[21];
    const float* hm_w2  = (const float*)d_in[27];
    const float* hm_b2  = (const float*)d_in[28];
    const float* r3w    = (const float*)d_in[29];
    const float* r3b    = (const float*)d_in[30];

    float* out = (float*)d_out;

    prep_kernel<<<1, 1024>>>(
        (const float*)d_in[4],  (const float*)d_in[5],  (const float*)d_in[6],  (const float*)d_in[7],  (const float*)d_in[8],   // hm
        (const float*)d_in[10], (const float*)d_in[11], (const float*)d_in[12], (const float*)d_in[13], (const float*)d_in[14],  // dep
        (const float*)d_in[16], (const float*)d_in[17], (const float*)d_in[18], (const float*)d_in[19], (const float*)d_in[20],  // dim
        (const float*)d_in[22], (const float*)d_in[23], (const float*)d_in[24], (const float*)d_in[25], (const float*)d_in[26],  // rot
        r3w);

    dim3 cgrid(Wn/64, Hn/4, Bn*8);
    conv3x3_bn_relu<<<cgrid, 256>>>(up4, hm_w1,  0, nullptr);          // -> g_hmh
    conv3x3_bn_relu<<<cgrid, 256>>>(up4, dep_w1, 1, out + OFF_DEP);
    conv3x3_bn_relu<<<cgrid, 256>>>(up4, dim_w1, 2, out + OFF_DIM);
    conv3x3_bn_relu<<<cgrid, 256>>>(up4, rot_w1, 3, out + OFF_ROT);

    heat_kernel<<<dim3(HWn/256, Bn), 256>>>(hm_w2, hm_b2, out);
    nms_kernel<<<(HEAT_N + 255)/256, 256>>>(out + OFF_HEAT);
    topk_class_kernel<<<Bn*NCn, 1024>>>();
    merge_kernel<<<Bn, 256>>>(out);
    gather_kernel<<<Bn*Kn, 384>>>(up8, up16, out);
    reg3d_kernel<<<(REG3D_N + 511)/512, 512>>>(r3b, out);
}

// round 4
// speedup vs baseline: 2.2870x; 2.2870x over previous
#include <cuda_runtime.h>
#include <math.h>
#include <stdint.h>

#define Bn   4
#define Hn   96
#define Wn   320
#define HWn  30720
#define CINn 64
#define HCn  256
#define NCn  3
#define Kn   100
#define NSTAGE 18

#define MAP_N      (Bn*HCn*HWn)
#define HEAT_N     (Bn*NCn*HWn)
#define OFF_HEAT   0
#define OFF_DEP    (OFF_HEAT + HEAT_N)
#define OFF_DIM    (OFF_DEP + MAP_N)
#define OFF_ROT    (OFF_DIM + MAP_N)
#define OFF_SCORES (OFF_ROT + MAP_N)
#define OFF_POIS   (OFF_SCORES + Bn*Kn)
#define OFF_REG3D  (OFF_POIS + Bn*Kn*384)
#define REG3D_N    (8*8*64*320)

__device__ float g_nms[HEAT_N];
__device__ float g_alpha[4*HCn];
__device__ float g_beta[4*HCn];
__device__ float g_wB[3*NSTAGE*8192];   // dep/dim/rot, fragment-order tf32
__device__ float g_wHi[NSTAGE*8192];    // hm hi
__device__ float g_wLo[NSTAGE*8192];    // hm lo
__device__ float g_cval[Bn*NCn*Kn];
__device__ int   g_cind[Bn*NCn*Kn];
__device__ int   g_sel[Bn*Kn];
__device__ float g_rs[8];

__device__ __forceinline__ uint32_t f2tf32(float f) {
    uint32_t r; asm("cvt.rna.tf32.f32 %0, %1;" : "=r"(r) : "f"(f)); return r;
}
__device__ __forceinline__ uint32_t fu(float f) { return __float_as_uint(f); }

__device__ __forceinline__ void cp16(void* dst, const void* src) {
    unsigned d = (unsigned)__cvta_generic_to_shared(dst);
    asm volatile("cp.async.cg.shared.global [%0], [%1], 16;" :: "r"(d), "l"(src));
}
#define CP_COMMIT() asm volatile("cp.async.commit_group;")
#define CP_WAIT(n)  asm volatile("cp.async.wait_group %0;" :: "n"(n))

__device__ __forceinline__ void mma8(float* c, const uint32_t* a, uint32_t b0, uint32_t b1) {
    asm volatile("mma.sync.aligned.m16n8k8.row.col.f32.tf32.tf32.f32 "
        "{%0,%1,%2,%3}, {%4,%5,%6,%7}, {%8,%9}, {%0,%1,%2,%3};"
        : "+f"(c[0]), "+f"(c[1]), "+f"(c[2]), "+f"(c[3])
        : "r"(a[0]), "r"(a[1]), "r"(a[2]), "r"(a[3]), "r"(b0), "r"(b1));
}

// ---------------- prep ----------------
__global__ void prep_kernel(
    const float* b1_0, const float* g_0, const float* be_0, const float* m_0, const float* v_0,
    const float* b1_1, const float* g_1, const float* be_1, const float* m_1, const float* v_1,
    const float* b1_2, const float* g_2, const float* be_2, const float* m_2, const float* v_2,
    const float* b1_3, const float* g_3, const float* be_3, const float* m_3, const float* v_3,
    const float* r3w)
{
    int t = threadIdx.x;
    const float* B1[4] = {b1_0, b1_1, b1_2, b1_3};
    const float* G [4] = {g_0,  g_1,  g_2,  g_3 };
    const float* BE[4] = {be_0, be_1, be_2, be_3};
    const float* M [4] = {m_0,  m_1,  m_2,  m_3 };
    const float* V [4] = {v_0,  v_1,  v_2,  v_3 };
    int h = t >> 8, c = t & 255;
    float inv = G[h][c] * rsqrtf(V[h][c] + 1e-5f);
    g_alpha[t] = inv;
    g_beta[t]  = (B1[h][c] - M[h][c]) * inv + BE[h][c];
    if (t < 8) {
        float s = 0.f;
        for (int i = 0; i < 64; ++i) s += r3w[t*64 + i];
        g_rs[t] = s;
    }
}

// fragment-order source fetch: dest (s, n, idx2, which)
__device__ __forceinline__ float wsrc(const float* w, int s, int n, int idx2, int which) {
    int c   = idx2 & 3;
    int kc  = (idx2 >> 2) ^ (n & 3);
    int k   = kc*8 + c + 4*which;
    int ch  = (s & 1)*32 + k;
    int pos = s >> 1;
    return w[n*576 + ch*9 + pos];
}

__global__ void pack1_kernel(const float* __restrict__ w1, const float* __restrict__ w2,
                             const float* __restrict__ w3)
{
    int idx = blockIdx.x * 256 + threadIdx.x;
    if (idx >= 3*NSTAGE*8192) return;
    int h = idx / (NSTAGE*8192);
    int r = idx - h*(NSTAGE*8192);
    int s = r >> 13, q = r & 8191;
    int which = q & 1, f2 = q >> 1;
    int n = f2 >> 4, idx2 = f2 & 15;
    const float* w = (h==0) ? w1 : (h==1) ? w2 : w3;
    g_wB[idx] = __uint_as_float(f2tf32(wsrc(w, s, n, idx2, which)));
}

__global__ void pack0_kernel(const float* __restrict__ w0)
{
    int idx = blockIdx.x * 256 + threadIdx.x;
    if (idx >= NSTAGE*8192) return;
    int s = idx >> 13, q = idx & 8191;
    int which = q & 1, f2 = q >> 1;
    int n = f2 >> 4, idx2 = f2 & 15;
    float v = wsrc(w0, s, n, idx2, which);
    uint32_t hi = f2tf32(v);
    float lo = v - __uint_as_float(hi);
    g_wHi[idx] = __uint_as_float(hi);
    g_wLo[idx] = __uint_as_float(f2tf32(lo));
}

// ---------------- tf32 conv for dep/dim/rot ----------------
// smem: A 2x16KB @0, B 2x32KB @32768, alpha @98304, beta @99328
#define T_SMEM 100352

__global__ void __launch_bounds__(256) conv_tf32(
    const float* __restrict__ X, float* __restrict__ out)
{
    extern __shared__ char sm[];
    float2* smA2 = (float2*)sm;
    float2* smB2 = (float2*)(sm + 32768);
    float*  sal  = (float*)(sm + 98304);
    float*  sbe  = (float*)(sm + 99328);

    const int tid  = threadIdx.x;
    const int lane = tid & 31;
    const int w    = tid >> 5;
    const int wm = w >> 2, wn = w & 3;
    const int g  = lane >> 2, cc = lane & 3, gm3 = g & 3;
    const int hidx = blockIdx.y;           // 0..2 -> heads 1..3
    const int mtile = blockIdx.x;

    sal[tid] = g_alpha[(hidx+1)*HCn + tid];
    sbe[tid] = g_beta [(hidx+1)*HCn + tid];

    const int mp = tid >> 1;               // m-row 0..127
    const int hf = tid & 1;
    const int mg = mtile*128 + mp;
    const int b  = mg / HWn;
    const int rem = mg - b*HWn;
    const int y0 = rem / Wn;
    const int x0 = rem - y0*Wn;
    const float* Xb = X + (size_t)b * CINn * HWn;
    const int cw = (lane >> 3) + 2*(lane & 1);   // write-order offset

    const float* wbase = g_wB + (size_t)hidx*NSTAGE*8192;

    float pre[16];
    float acc[4][8][4];
    #pragma unroll
    for (int i=0;i<4;++i)
        #pragma unroll
        for (int j=0;j<8;++j)
            #pragma unroll
            for (int k=0;k<4;++k) acc[i][j][k]=0.f;

    auto loadA = [&](int s) {
        int p = s >> 1;
        int ky = p/3, kx = p - ky*3;
        int gy = y0 + ky - 1, gx = x0 + kx - 1;
        bool valid = ((unsigned)gy < (unsigned)Hn) && ((unsigned)gx < (unsigned)Wn);
        const float* src = Xb + (size_t)((s&1)*32 + hf*16)*HWn + gy*Wn + gx;
        #pragma unroll
        for (int j=0;j<16;++j) pre[j] = valid ? src[(size_t)j*HWn] : 0.f;
    };
    auto loadB = [&](int s, int buf) {
        const float* src = wbase + (size_t)s*8192;
        char* dst = (char*)smB2 + (size_t)buf*32768;
        #pragma unroll
        for (int i=0;i<8;++i) {
            int ch = tid + i*256;
            cp16(dst + ch*16, src + ch*4);
        }
    };
    auto stsA = [&](int buf) {
        float2* base = smA2 + buf*2048 + mp*16;
        #pragma unroll
        for (int u=0;u<8;++u) {
            int kcl = u >> 2;
            int c = ((u & 3) + cw) & 3;
            int kc = 2*hf + kcl;
            float2 v = make_float2(
                __uint_as_float(f2tf32(pre[kcl*8 + c])),
                __uint_as_float(f2tf32(pre[kcl*8 + c + 4])));
            base[((kc ^ (mp & 3)) << 2) + c] = v;
        }
    };

    loadA(0);
    loadB(0, 0); CP_COMMIT();

    for (int s = 0; s < NSTAGE; ++s) {
        const int buf = s & 1;
        stsA(buf);
        if (s < NSTAGE-1) {
            loadA(s+1);
            loadB(s+1, buf ^ 1); CP_COMMIT();
            CP_WAIT(1);
        } else {
            CP_WAIT(0);
        }
        __syncthreads();

        const float2* A2 = smA2 + buf*2048;
        const float2* B2 = smB2 + buf*4096;
        #pragma unroll
        for (int kc=0;kc<4;++kc) {
            const int sw = ((kc ^ gm3) << 2) + cc;
            uint32_t a[4][4];
            #pragma unroll
            for (int m2=0;m2<4;++m2) {
                int base = (wm*64 + m2*16 + g)*16 + sw;
                float2 qa = A2[base];
                float2 qb = A2[base + 128];
                a[m2][0]=fu(qa.x); a[m2][1]=fu(qb.x); a[m2][2]=fu(qa.y); a[m2][3]=fu(qb.y);
            }
            #pragma unroll
            for (int n2=0;n2<8;++n2) {
                float2 bb = B2[(wn*64 + n2*8 + g)*16 + sw];
                uint32_t b0 = fu(bb.x), b1 = fu(bb.y);
                #pragma unroll
                for (int m2=0;m2<4;++m2) mma8(acc[m2][n2], a[m2], b0, b1);
            }
        }
    }

    // epilogue: BN+ReLU -> smem transpose -> coalesced float4 stores
    const int bT = (mtile*128) / HWn;
    const int pT = mtile*128 - bT*HWn;
    float* obase = out + OFF_DEP + (size_t)hidx*MAP_N + (size_t)bT*HCn*HWn + pT;
    float* chunk = (float*)sm;             // 64 x 132

    for (int c = 0; c < 4; ++c) {
        __syncthreads();
        if (wn == c) {
            #pragma unroll
            for (int m2=0;m2<4;++m2)
                #pragma unroll
                for (int n2=0;n2<8;++n2)
                    #pragma unroll
                    for (int e=0;e<4;++e) {
                        int mrow = wm*64 + m2*16 + g + (e>>1)*8;
                        int ocl  = n2*8 + 2*cc + (e&1);
                        int oc   = c*64 + ocl;
                        float v = fmaxf(fmaf(acc[m2][n2][e], sal[oc], sbe[oc]), 0.f);
                        chunk[ocl*132 + mrow] = v;
                    }
        }
        __syncthreads();
        const float* sp = chunk + (tid>>2)*132 + (tid&3)*32;
        float* dst = obase + (size_t)(c*64 + (tid>>2))*HWn + (tid&3)*32;
        #pragma unroll
        for (int i=0;i<8;++i)
            ((float4*)dst)[i] = ((const float4*)sp)[i];
    }
}

// ---------------- hm conv: 3xTF32 + fused 1x1 + sigmoid ----------------
// smem: Ah 16K @0, Al 16K @16384, Bh 32K @32768, Bl 32K @65536,
//       alpha @98304, beta @99328, w2 @100352, hmbuf @103424
#define H_SMEM 104960

__global__ void __launch_bounds__(256) conv_hm(
    const float* __restrict__ X, float* __restrict__ out,
    const float* __restrict__ hm_w2, const float* __restrict__ hm_b2)
{
    extern __shared__ char sm[];
    float2* smAh = (float2*)sm;
    float2* smAl = (float2*)(sm + 16384);
    float2* smBh = (float2*)(sm + 32768);
    float2* smBl = (float2*)(sm + 65536);
    float*  sal  = (float*)(sm + 98304);
    float*  sbe  = (float*)(sm + 99328);
    float*  sw2  = (float*)(sm + 100352);
    float*  hmbuf= (float*)(sm + 103424);

    const int tid  = threadIdx.x;
    const int lane = tid & 31;
    const int w    = tid >> 5;
    const int wm = w >> 2, wn = w & 3;
    const int g  = lane >> 2, cc = lane & 3, gm3 = g & 3;
    const int mtile = blockIdx.x;

    sal[tid] = g_alpha[tid];
    sbe[tid] = g_beta [tid];
    sw2[tid]       = hm_w2[tid];
    sw2[tid + 256] = hm_w2[tid + 256];
    sw2[tid + 512] = hm_w2[tid + 512];
    if (tid < 128) { hmbuf[tid*3]=0.f; hmbuf[tid*3+1]=0.f; hmbuf[tid*3+2]=0.f; }

    const int mp = tid >> 1;
    const int hf = tid & 1;
    const int mg = mtile*128 + mp;
    const int b  = mg / HWn;
    const int rem = mg - b*HWn;
    const int y0 = rem / Wn;
    const int x0 = rem - y0*Wn;
    const float* Xb = X + (size_t)b * CINn * HWn;
    const int cw = (lane >> 3) + 2*(lane & 1);

    float acc[4][8][4];
    #pragma unroll
    for (int i=0;i<4;++i)
        #pragma unroll
        for (int j=0;j<8;++j)
            #pragma unroll
            for (int k=0;k<4;++k) acc[i][j][k]=0.f;

    for (int s = 0; s < NSTAGE; ++s) {
        __syncthreads();   // protect previous stage reads
        // A hi/lo staging
        {
            int p = s >> 1;
            int ky = p/3, kx = p - ky*3;
            int gy = y0 + ky - 1, gx = x0 + kx - 1;
            bool valid = ((unsigned)gy < (unsigned)Hn) && ((unsigned)gx < (unsigned)Wn);
            const float* src = Xb + (size_t)((s&1)*32 + hf*16)*HWn + gy*Wn + gx;
            float pre[16];
            #pragma unroll
            for (int j=0;j<16;++j) pre[j] = valid ? src[(size_t)j*HWn] : 0.f;
            float2* bh = smAh + mp*16;
            float2* bl = smAl + mp*16;
            #pragma unroll
            for (int u=0;u<8;++u) {
                int kcl = u >> 2;
                int c = ((u & 3) + cw) & 3;
                int kc = 2*hf + kcl;
                float v0 = pre[kcl*8 + c], v1 = pre[kcl*8 + c + 4];
                uint32_t h0 = f2tf32(v0), h1 = f2tf32(v1);
                float l0 = v0 - __uint_as_float(h0);
                float l1 = v1 - __uint_as_float(h1);
                int idx2 = ((kc ^ (mp & 3)) << 2) + c;
                bh[idx2] = make_float2(__uint_as_float(h0), __uint_as_float(h1));
                bl[idx2] = make_float2(__uint_as_float(f2tf32(l0)), __uint_as_float(f2tf32(l1)));
            }
        }
        // B hi/lo via cp.async
        {
            const float* sh = g_wHi + (size_t)s*8192;
            const float* sl = g_wLo + (size_t)s*8192;
            #pragma unroll
            for (int i=0;i<8;++i) {
                int ch = tid + i*256;
                cp16((char*)smBh + ch*16, sh + ch*4);
                cp16((char*)smBl + ch*16, sl + ch*4);
            }
            CP_COMMIT();
            CP_WAIT(0);
        }
        __syncthreads();

        const float2* Ap[3] = { smAh, smAl, smAh };
        const float2* Bp[3] = { smBh, smBh, smBl };
        #pragma unroll
        for (int ps=0; ps<3; ++ps) {
            const float2* A2 = Ap[ps];
            const float2* B2 = Bp[ps];
            #pragma unroll
            for (int kc=0;kc<4;++kc) {
                const int swz = ((kc ^ gm3) << 2) + cc;
                uint32_t a[4][4];
                #pragma unroll
                for (int m2=0;m2<4;++m2) {
                    int base = (wm*64 + m2*16 + g)*16 + swz;
                    float2 qa = A2[base];
                    float2 qb = A2[base + 128];
                    a[m2][0]=fu(qa.x); a[m2][1]=fu(qb.x); a[m2][2]=fu(qa.y); a[m2][3]=fu(qb.y);
                }
                #pragma unroll
                for (int n2=0;n2<8;++n2) {
                    float2 bb = B2[(wn*64 + n2*8 + g)*16 + swz];
                    uint32_t b0 = fu(bb.x), b1 = fu(bb.y);
                    #pragma unroll
                    for (int m2=0;m2<4;++m2) mma8(acc[m2][n2], a[m2], b0, b1);
                }
            }
        }
    }

    // epilogue: BN+ReLU -> 1x1(3 classes) -> sigmoid
    float hmacc[8][3];
    #pragma unroll
    for (int i=0;i<8;++i) { hmacc[i][0]=0.f; hmacc[i][1]=0.f; hmacc[i][2]=0.f; }

    #pragma unroll
    for (int m2=0;m2<4;++m2)
        #pragma unroll
        for (int n2=0;n2<8;++n2)
            #pragma unroll
            for (int e=0;e<4;++e) {
                int oc = wn*64 + n2*8 + 2*cc + (e&1);
                float v = fmaxf(fmaf(acc[m2][n2][e], sal[oc], sbe[oc]), 0.f);
                int r = m2*2 + (e>>1);
                hmacc[r][0] = fmaf(sw2[oc],       v, hmacc[r][0]);
                hmacc[r][1] = fmaf(sw2[256 + oc], v, hmacc[r][1]);
                hmacc[r][2] = fmaf(sw2[512 + oc], v, hmacc[r][2]);
            }
    #pragma unroll
    for (int o=1;o<4;o<<=1)
        #pragma unroll
        for (int i=0;i<8;++i)
            #pragma unroll
            for (int j=0;j<3;++j)
                hmacc[i][j] += __shfl_xor_sync(0xffffffffu, hmacc[i][j], o);

    __syncthreads();
    if (cc == 0) {
        #pragma unroll
        for (int m2=0;m2<4;++m2)
            #pragma unroll
            for (int t=0;t<2;++t) {
                int mrow = wm*64 + m2*16 + g + t*8;
                #pragma unroll
                for (int j=0;j<3;++j)
                    atomicAdd(&hmbuf[mrow*3 + j], hmacc[m2*2+t][j]);
            }
    }
    __syncthreads();

    if (tid < 128) {
        int m2g = mtile*128 + tid;
        int b2 = m2g / HWn;
        int p2 = m2g - b2*HWn;
        #pragma unroll
        for (int j=0;j<3;++j) {
            float h = hmbuf[tid*3 + j] + hm_b2[j];
            out[OFF_HEAT + (b2*NCn + j)*HWn + p2] = 1.f / (1.f + expf(-h));
        }
    }
}

// ---------------- NMS ----------------
__global__ void nms_kernel(const float* __restrict__ heat)
{
    int idx = blockIdx.x * blockDim.x + threadIdx.x;
    if (idx >= HEAT_N) return;
    int bc = idx / HWn;
    int p  = idx - bc * HWn;
    int y = p / Wn, x = p - y * Wn;
    const float* base = heat + bc * HWn;
    float c = base[p];
    float mx = c;
    #pragma unroll
    for (int dy = -1; dy <= 1; ++dy) {
        int yy = y + dy;
        if ((unsigned)yy >= (unsigned)Hn) continue;
        #pragma unroll
        for (int dx = -1; dx <= 1; ++dx) {
            int xx = x + dx;
            if ((unsigned)xx >= (unsigned)Wn) continue;
            float v = base[yy * Wn + xx];
            if (v > mx) mx = v;
        }
    }
    g_nms[idx] = (c == mx) ? c : 0.f;
}

// ---------------- per-(b,c) top-100 ----------------
__global__ void __launch_bounds__(1024) topk_class_kernel()
{
    int bc  = blockIdx.x;
    int tid = threadIdx.x;
    float v[30];
    const float* src = g_nms + bc * HWn;
    #pragma unroll
    for (int j = 0; j < 30; ++j) v[j] = src[j*1024 + tid];

    __shared__ unsigned long long swarp[32];
    __shared__ unsigned long long swin;

    for (int it = 0; it < Kn; ++it) {
        float bv = -1.f; int bj = 0;
        #pragma unroll
        for (int j = 0; j < 30; ++j) { if (v[j] > bv) { bv = v[j]; bj = j; } }
        unsigned vb = (bv > 0.f) ? __float_as_uint(bv) : 0u;
        unsigned long long key = ((unsigned long long)vb << 32) | (unsigned)(bj*1024 + tid);

        unsigned long long k = key;
        #pragma unroll
        for (int off = 16; off > 0; off >>= 1) {
            unsigned long long o = __shfl_down_sync(0xffffffffu, k, off);
            if (o > k) k = o;
        }
        if ((tid & 31) == 0) swarp[tid >> 5] = k;
        __syncthreads();
        if (tid < 32) {
            unsigned long long k2 = swarp[tid];
            #pragma unroll
            for (int off = 16; off > 0; off >>= 1) {
                unsigned long long o = __shfl_down_sync(0xffffffffu, k2, off);
                if (o > k2) k2 = o;
            }
            if (tid == 0) swin = k2;
        }
        __syncthreads();
        unsigned long long win = swin;
        if (tid == 0) {
            g_cval[bc*Kn + it] = __uint_as_float((unsigned)(win >> 32));
            g_cind[bc*Kn + it] = (int)(win & 0xffffffffu);
        }
        if (key == win) {
            #pragma unroll
            for (int j = 0; j < 30; ++j) { if (j == bj) v[j] = -1.f; }
        }
        __syncthreads();
    }
}

// ---------------- per-b merge ----------------
__global__ void __launch_bounds__(256) merge_kernel(float* __restrict__ out)
{
    int b = blockIdx.x, tid = threadIdx.x;
    __shared__ float sv[300];
    __shared__ int   si[300];
    __shared__ unsigned long long swarp[8];
    for (int i = tid; i < 300; i += 256) {
        int cls = i / Kn, j = i % Kn;
        sv[i] = g_cval[(b*NCn + cls)*Kn + j];
        si[i] = g_cind[(b*NCn + cls)*Kn + j];
    }
    __syncthreads();
    for (int it = 0; it < Kn; ++it) {
        float bv = -1.f; int bi = -1;
        for (int i = tid; i < 300; i += 256) { if (sv[i] > bv) { bv = sv[i]; bi = i; } }
        unsigned vb = (bv > 0.f) ? __float_as_uint(bv) : 0u;
        unsigned long long k = ((unsigned long long)vb << 32) | (unsigned)(bi + 1);
        #pragma unroll
        for (int off = 16; off > 0; off >>= 1) {
            unsigned long long o = __shfl_down_sync(0xffffffffu, k, off);
            if (o > k) k = o;
        }
        if ((tid & 31) == 0) swarp[tid >> 5] = k;
        __syncthreads();
        if (tid == 0) {
            unsigned long long win = swarp[0];
            #pragma unroll
            for (int ww = 1; ww < 8; ++ww) { if (swarp[ww] > win) win = swarp[ww]; }
            int slot = (int)(win & 0xffffffffu) - 1;
            out[OFF_SCORES + b*Kn + it] = __uint_as_float((unsigned)(win >> 32));
            g_sel[b*Kn + it] = si[slot];
            sv[slot] = -1.f;
        }
        __syncthreads();
    }
}

// ---------------- gather ----------------
__global__ void __launch_bounds__(384) gather_kernel(
    const float* __restrict__ up8, const float* __restrict__ up16, float* __restrict__ out)
{
    int bk = blockIdx.x;
    int b  = bk / Kn;
    int c  = threadIdx.x;
    int ind = g_sel[bk];
    if (ind < 0) ind = 0;
    if (ind > HWn - 1) ind = HWn - 1;
    float val;
    if (c < 128)
        val = up8 [((long long)b*128 + c)       * HWn + (ind >> 1)];
    else
        val = up16[((long long)b*256 + (c-128)) * HWn + (ind >> 2)];
    out[OFF_POIS + bk*384 + c] = val;
}

// ---------------- reg3d ----------------
__global__ void reg3d_kernel(const float* __restrict__ r3b, float* __restrict__ out)
{
    int idx = blockIdx.x * blockDim.x + threadIdx.x;
    if (idx >= REG3D_N) return;
    int o = (idx / (64*320)) & 7;
    out[OFF_REG3D + idx] = g_rs[o] + r3b[o];
}

// ---------------- launch ----------------
extern "C" void kernel_launch(void* const* d_in, const int* in_sizes, int n_in,
                              void* d_out, int out_size)
{
    const float* up16 = (const float*)d_in[0];
    const float* up8  = (const float*)d_in[1];
    const float* up4  = (const float*)d_in[2];

    const float* hm_w1  = (const float*)d_in[3];
    const float* dep_w1 = (const float*)d_in[9];
    const float* dim_w1 = (const float*)d_in[15];
    const float* rot_w1 = (const float*)d_in[21];
    const float* hm_w2  = (const float*)d_in[27];
    const float* hm_b2  = (const float*)d_in[28];
    const float* r3w    = (const float*)d_in[29];
    const float* r3b    = (const float*)d_in[30];

    float* out = (float*)d_out;

    cudaFuncSetAttribute(conv_tf32, cudaFuncAttributeMaxDynamicSharedMemorySize, T_SMEM);
    cudaFuncSetAttribute(conv_hm,   cudaFuncAttributeMaxDynamicSharedMemorySize, H_SMEM);

    prep_kernel<<<1, 1024>>>(
        (const float*)d_in[4],  (const float*)d_in[5],  (const float*)d_in[6],  (const float*)d_in[7],  (const float*)d_in[8],
        (const float*)d_in[10], (const float*)d_in[11], (const float*)d_in[12], (const float*)d_in[13], (const float*)d_in[14],
        (const float*)d_in[16], (const float*)d_in[17], (const float*)d_in[18], (const float*)d_in[19], (const float*)d_in[20],
        (const float*)d_in[22], (const float*)d_in[23], (const float*)d_in[24], (const float*)d_in[25], (const float*)d_in[26],
        r3w);
    pack1_kernel<<<(3*NSTAGE*8192 + 255)/256, 256>>>(dep_w1, dim_w1, rot_w1);
    pack0_kernel<<<(NSTAGE*8192 + 255)/256, 256>>>(hm_w1);

    conv_tf32<<<dim3(960, 3), 256, T_SMEM>>>(up4, out);
    conv_hm<<<960, 256, H_SMEM>>>(up4, out, hm_w2, hm_b2);

    nms_kernel<<<(HEAT_N + 255)/256, 256>>>(out + OFF_HEAT);
    topk_class_kernel<<<Bn*NCn, 1024>>>();
    merge_kernel<<<Bn, 256>>>(out);
    gather_kernel<<<Bn*Kn, 384>>>(up8, up16, out);
    reg3d_kernel<<<(REG3D_N + 511)/512, 512>>>(r3b, out);
}